// round 5
// baseline (speedup 1.0000x reference)
#include <cuda_runtime.h>
#include <math.h>

#define N_NODES 50000
#define N_EDGES 800000
#define HID 128
#define ANF 32
#define EPSV 1e-12f

typedef unsigned long long ull;

// -------- scratch (no allocations allowed; device globals) --------
__device__ float g_hA[N_NODES * HID];    // h @ e_w1[0:128,:]
__device__ float g_hB[N_NODES * HID];    // h @ e_w1[128:256,:]
__device__ float g_sum[N_NODES * HID];   // scatter-sum accumulator
__device__ float g_cnt[N_NODES];         // edge counts (float)

// -------- packed f32x2 helpers (FFMA2 is PTX-only) --------
__device__ __forceinline__ ull pack2(float x, float y) {
    ull r;
    asm("mov.b64 %0,{%1,%2};" : "=l"(r) : "r"(__float_as_uint(x)), "r"(__float_as_uint(y)));
    return r;
}
__device__ __forceinline__ float2 unpack2(ull v) {
    unsigned a, b;
    asm("mov.b64 {%0,%1},%2;" : "=r"(a), "=r"(b) : "l"(v));
    return make_float2(__uint_as_float(a), __uint_as_float(b));
}
__device__ __forceinline__ ull fma2(ull a, ull b, ull c) {
    ull d;
    asm("fma.rn.f32x2 %0,%1,%2,%3;" : "=l"(d) : "l"(a), "l"(b), "l"(c));
    return d;
}
__device__ __forceinline__ float silu(float x) { return x / (1.0f + __expf(-x)); }

// ============================================================================
// Kernel 1: hA = h @ W1a, hB = h @ W1b   (per-node precompute of edge layer 1)
// 128 threads, 32 nodes per block, 4 nodes at a time (f32x2 over node pairs).
// ============================================================================
#define HAB_SMEM_FLOATS (16384 + 16384 + 512)
__global__ void hab_kernel(const float* __restrict__ h,
                           const float* __restrict__ e_w1,
                           float* __restrict__ hA, float* __restrict__ hB) {
    extern __shared__ float s[];
    float* wA = s;               // 16384  e_w1 rows 0..127   [k*128+t]
    float* wB = wA + 16384;      // 16384  e_w1 rows 128..255
    float* hq = wB + 16384;      // 512    4 node rows, transposed [k*4+m]
    const int tid = threadIdx.x;

    for (int i = tid; i < 16384; i += 128) {
        wA[i] = e_w1[i];
        wB[i] = e_w1[16384 + i];
    }
    __syncthreads();

    const int n0 = blockIdx.x * 32;
    for (int sub = 0; sub < 32; sub += 4) {
        const int nb = n0 + sub;
        for (int idx = tid; idx < 512; idx += 128) {
            const int m = idx >> 7, k = idx & 127;
            hq[k * 4 + m] = (nb + m < N_NODES) ? h[(nb + m) * HID + k] : 0.0f;
        }
        __syncthreads();

        ull a01 = 0ull, a23 = 0ull, b01 = 0ull, b23 = 0ull;
#pragma unroll 4
        for (int k = 0; k < HID; k++) {
            const float4 hv = *(const float4*)&hq[k * 4];
            const ull h01 = pack2(hv.x, hv.y);
            const ull h23 = pack2(hv.z, hv.w);
            const float wa = wA[k * HID + tid];
            const float wb = wB[k * HID + tid];
            const ull wa2 = pack2(wa, wa);
            const ull wb2 = pack2(wb, wb);
            a01 = fma2(h01, wa2, a01);
            a23 = fma2(h23, wa2, a23);
            b01 = fma2(h01, wb2, b01);
            b23 = fma2(h23, wb2, b23);
        }
        float2 f;
        f = unpack2(a01);
        if (nb + 0 < N_NODES) hA[(nb + 0) * HID + tid] = f.x;
        if (nb + 1 < N_NODES) hA[(nb + 1) * HID + tid] = f.y;
        f = unpack2(a23);
        if (nb + 2 < N_NODES) hA[(nb + 2) * HID + tid] = f.x;
        if (nb + 3 < N_NODES) hA[(nb + 3) * HID + tid] = f.y;
        f = unpack2(b01);
        if (nb + 0 < N_NODES) hB[(nb + 0) * HID + tid] = f.x;
        if (nb + 1 < N_NODES) hB[(nb + 1) * HID + tid] = f.y;
        f = unpack2(b23);
        if (nb + 2 < N_NODES) hB[(nb + 2) * HID + tid] = f.x;
        if (nb + 3 < N_NODES) hB[(nb + 3) * HID + tid] = f.y;
        __syncthreads();
    }
}

// ============================================================================
// Kernel 2: edge MLP + scatter.  256 threads, 16 edges/group (two 128-thread
// halves, each 8 edges), shared W2 tile amortized over 2x warps vs v1.
// pre = hA[row] + hB[col] + b1 + attr @ W1c ; ef1 = silu(pre)
// ef2 = silu(ef1 @ W2 + b2) ; atomic scatter-sum into g_sum[row], count++
// ============================================================================
#define EG 16   // edges per group
#define EH 8    // edges per half
#define EDGE_SMEM_FLOATS (16384 + 4096 + 128 + 128 + EG * ANF + HID * EG + 32)
__global__ void edge_kernel(const float* __restrict__ hA, const float* __restrict__ hB,
                            const int* __restrict__ row_idx, const int* __restrict__ col_idx,
                            const float* __restrict__ edge_attr,
                            const float* __restrict__ e_w1,  // base; W1c at rows 256..287
                            const float* __restrict__ e_b1,
                            const float* __restrict__ e_w2,
                            const float* __restrict__ e_b2,
                            float* __restrict__ gsum, float* __restrict__ gcnt) {
    extern __shared__ float s[];
    float* w2     = s;                 // 16384 [k*128+t]
    float* w1c    = w2 + 16384;        // 4096  e_w1 rows 256..287 [k*128+t]
    float* b1     = w1c + 4096;        // 128
    float* b2     = b1 + 128;          // 128
    float* attr_t = b2 + 128;          // EG*ANF [k*EG+e]
    float* ef1t   = attr_t + EG * ANF; // HID*EG [k*EG+e]
    int*   rows   = (int*)(ef1t + HID * EG);  // EG
    int*   cols   = rows + EG;                // EG
    const int tid = threadIdx.x;
    const int t   = tid & 127;   // feature
    const int eh  = tid >> 7;    // edge-half 0/1

    for (int i = tid; i < 16384; i += 256) w2[i] = e_w2[i];
    for (int i = tid; i < 4096; i += 256) w1c[i] = e_w1[32768 + i];
    if (tid < 128) { b1[tid] = e_b1[tid]; b2[tid] = e_b2[tid]; }
    __syncthreads();

    const int ngroups = N_EDGES / EG;  // 50000
    for (int g = blockIdx.x; g < ngroups; g += gridDim.x) {
        const int e0 = g * EG;
        if (tid < EG) {
            rows[tid] = row_idx[e0 + tid];
            cols[tid] = col_idx[e0 + tid];
        }
        // load edge_attr for 16 edges, transposed (coalesced read)
        for (int idx = tid; idx < EG * ANF; idx += 256) {
            const int e = idx >> 5, k = idx & 31;
            attr_t[k * EG + e] = edge_attr[(e0 + e) * ANF + k];
        }
        __syncthreads();

        const int* myrows = rows + eh * EH;
        const int* mycols = cols + eh * EH;

        // -------- layer 1 --------
        const float bb = b1[t];
        float pre[EH];
#pragma unroll
        for (int e = 0; e < EH; e++) {
            pre[e] = hA[myrows[e] * HID + t] + hB[mycols[e] * HID + t] + bb;
        }
        ull p01 = pack2(pre[0], pre[1]);
        ull p23 = pack2(pre[2], pre[3]);
        ull p45 = pack2(pre[4], pre[5]);
        ull p67 = pack2(pre[6], pre[7]);
#pragma unroll 4
        for (int k = 0; k < ANF; k++) {
            const float w = w1c[k * HID + t];
            const ull wv = pack2(w, w);
            const float4 a0 = *(const float4*)&attr_t[k * EG + eh * EH];
            const float4 a1 = *(const float4*)&attr_t[k * EG + eh * EH + 4];
            p01 = fma2(pack2(a0.x, a0.y), wv, p01);
            p23 = fma2(pack2(a0.z, a0.w), wv, p23);
            p45 = fma2(pack2(a1.x, a1.y), wv, p45);
            p67 = fma2(pack2(a1.z, a1.w), wv, p67);
        }
        {
            const float2 t0 = unpack2(p01), t1 = unpack2(p23);
            const float2 t2 = unpack2(p45), t3 = unpack2(p67);
            *(float4*)&ef1t[t * EG + eh * EH] =
                make_float4(silu(t0.x), silu(t0.y), silu(t1.x), silu(t1.y));
            *(float4*)&ef1t[t * EG + eh * EH + 4] =
                make_float4(silu(t2.x), silu(t2.y), silu(t3.x), silu(t3.y));
        }
        __syncthreads();

        // -------- layer 2 --------
        const float b2v = b2[t];
        ull acc01 = pack2(b2v, b2v);
        ull acc23 = acc01, acc45 = acc01, acc67 = acc01;
#pragma unroll 4
        for (int k = 0; k < HID; k++) {
            const float w = w2[k * HID + t];
            const ull wv = pack2(w, w);
            const float4 q0 = *(const float4*)&ef1t[k * EG + eh * EH];
            const float4 q1 = *(const float4*)&ef1t[k * EG + eh * EH + 4];
            acc01 = fma2(pack2(q0.x, q0.y), wv, acc01);
            acc23 = fma2(pack2(q0.z, q0.w), wv, acc23);
            acc45 = fma2(pack2(q1.x, q1.y), wv, acc45);
            acc67 = fma2(pack2(q1.z, q1.w), wv, acc67);
        }
        {
            const float2 o0 = unpack2(acc01), o1 = unpack2(acc23);
            const float2 o2 = unpack2(acc45), o3 = unpack2(acc67);
            const float ov[EH] = {o0.x, o0.y, o1.x, o1.y, o2.x, o2.y, o3.x, o3.y};
#pragma unroll
            for (int e = 0; e < EH; e++) {
                atomicAdd(&gsum[myrows[e] * HID + t], silu(ov[e]));
            }
        }
        if (tid < EG) atomicAdd(&gcnt[rows[tid]], 1.0f);
        __syncthreads();
    }
}

// ============================================================================
// Kernel 3: scatter-mean + two node MLPs + normalize/Gram-Schmidt/cross.
// 128 threads, 32 nodes per block, 4 at a time.
// ============================================================================
#define HSTRIDE 129
#define NODE_SMEM_FLOATS (16384 + 16384 + 384 + 384 + 128 + 128 + 4 + 4 + 512 + 8 * HSTRIDE + 24)
__global__ void node_kernel(const float* __restrict__ gsum, const float* __restrict__ gcnt,
                            const float* __restrict__ v1_w1, const float* __restrict__ v1_b1,
                            const float* __restrict__ v1_w2, const float* __restrict__ v1_b2,
                            const float* __restrict__ v2_w1, const float* __restrict__ v2_b1,
                            const float* __restrict__ v2_w2, const float* __restrict__ v2_b2,
                            float* __restrict__ out) {
    extern __shared__ float s[];
    float* wA  = s;                    // 16384  v1_w1 [k*128+t]
    float* wB  = wA + 16384;           // 16384  v2_w1
    float* w2a = wB + 16384;           // 384    v1_w2 [t*3+j]
    float* w2b = w2a + 384;            // 384    v2_w2
    float* b1a = w2b + 384;            // 128
    float* b1b = b1a + 128;            // 128
    float* b2a = b1b + 128;            // 4
    float* b2b = b2a + 4;              // 4
    float* nq  = b2b + 4;              // 512    [k*4+m]
    float* hid = nq + 512;             // 8*129  [(m*2+br)*129+t]
    float* vecs = hid + 8 * HSTRIDE;   // 24     [m*6 + br*3 + j]
    const int tid = threadIdx.x;

    for (int i = tid; i < 16384; i += 128) {
        wA[i] = v1_w1[i];
        wB[i] = v2_w1[i];
    }
    for (int i = tid; i < 384; i += 128) {
        w2a[i] = v1_w2[i];
        w2b[i] = v2_w2[i];
    }
    if (tid < 128) { b1a[tid] = v1_b1[tid]; b1b[tid] = v2_b1[tid]; }
    if (tid < 3)   { b2a[tid] = v1_b2[tid]; b2b[tid] = v2_b2[tid]; }
    __syncthreads();

    const int n0 = blockIdx.x * 32;
    for (int sub = 0; sub < 32; sub += 4) {
        const int nb = n0 + sub;
        for (int idx = tid; idx < 512; idx += 128) {
            const int m = idx >> 7, k = idx & 127;
            const int n = nb + m;
            float v = 0.0f;
            if (n < N_NODES) {
                const float c = gcnt[n];
                v = gsum[n * HID + k] / fmaxf(c, 1.0f);
            }
            nq[k * 4 + m] = v;
        }
        __syncthreads();

        const float ba = b1a[tid], bbv = b1b[tid];
        ull aA01 = pack2(ba, ba), aA23 = aA01;
        ull aB01 = pack2(bbv, bbv), aB23 = aB01;
#pragma unroll 4
        for (int k = 0; k < HID; k++) {
            const float4 hv = *(const float4*)&nq[k * 4];
            const ull h01 = pack2(hv.x, hv.y);
            const ull h23 = pack2(hv.z, hv.w);
            const float wa = wA[k * HID + tid];
            const float wb = wB[k * HID + tid];
            const ull wa2 = pack2(wa, wa);
            const ull wb2 = pack2(wb, wb);
            aA01 = fma2(h01, wa2, aA01);
            aA23 = fma2(h23, wa2, aA23);
            aB01 = fma2(h01, wb2, aB01);
            aB23 = fma2(h23, wb2, aB23);
        }
        {
            float2 f;
            f = unpack2(aA01);
            hid[(0 * 2 + 0) * HSTRIDE + tid] = silu(f.x);
            hid[(1 * 2 + 0) * HSTRIDE + tid] = silu(f.y);
            f = unpack2(aA23);
            hid[(2 * 2 + 0) * HSTRIDE + tid] = silu(f.x);
            hid[(3 * 2 + 0) * HSTRIDE + tid] = silu(f.y);
            f = unpack2(aB01);
            hid[(0 * 2 + 1) * HSTRIDE + tid] = silu(f.x);
            hid[(1 * 2 + 1) * HSTRIDE + tid] = silu(f.y);
            f = unpack2(aB23);
            hid[(2 * 2 + 1) * HSTRIDE + tid] = silu(f.x);
            hid[(3 * 2 + 1) * HSTRIDE + tid] = silu(f.y);
        }
        __syncthreads();

        if (tid < 24) {
            const int m = tid / 6, r = tid % 6, br = r / 3, j = r % 3;
            const float* hh = &hid[(m * 2 + br) * HSTRIDE];
            const float* ww = br ? w2b : w2a;
            float acc = br ? b2b[j] : b2a[j];
#pragma unroll 8
            for (int tt = 0; tt < HID; tt++) acc += hh[tt] * ww[tt * 3 + j];
            vecs[m * 6 + r] = acc;
        }
        __syncthreads();

        if (tid < 4 && nb + tid < N_NODES) {
            const float* v = &vecs[tid * 6];
            float v1x = v[0], v1y = v[1], v1z = v[2];
            float v2x = v[3], v2y = v[4], v2z = v[5];
            float n1 = fmaxf(sqrtf(v1x * v1x + v1y * v1y + v1z * v1z), EPSV);
            v1x /= n1; v1y /= n1; v1z /= n1;
            const float d = v2x * v1x + v2y * v1y + v2z * v1z;
            v2x -= d * v1x; v2y -= d * v1y; v2z -= d * v1z;
            float n2 = fmaxf(sqrtf(v2x * v2x + v2y * v2y + v2z * v2z), EPSV);
            v2x /= n2; v2y /= n2; v2z /= n2;
            const float cx = v1y * v2z - v1z * v2y;
            const float cy = v1z * v2x - v1x * v2z;
            const float cz = v1x * v2y - v1y * v2x;
            float* o = &out[(size_t)(nb + tid) * 9];
            o[0] = v1x; o[1] = v2x; o[2] = cx;
            o[3] = v1y; o[4] = v2y; o[5] = cy;
            o[6] = v1z; o[7] = v2z; o[8] = cz;
        }
        __syncthreads();
    }
}

// ============================================================================
// Launch
// ============================================================================
extern "C" void kernel_launch(void* const* d_in, const int* in_sizes, int n_in,
                              void* d_out, int out_size) {
    const float* h      = (const float*)d_in[0];
    // d_in[1] = x (unused by reference)
    const int*   eidx   = (const int*)d_in[2];
    const float* eattr  = (const float*)d_in[3];
    const float* e_w1   = (const float*)d_in[4];
    const float* e_b1   = (const float*)d_in[5];
    const float* e_w2   = (const float*)d_in[6];
    const float* e_b2   = (const float*)d_in[7];
    const float* v1_w1  = (const float*)d_in[8];
    const float* v1_b1  = (const float*)d_in[9];
    const float* v1_w2  = (const float*)d_in[10];
    const float* v1_b2  = (const float*)d_in[11];
    const float* v2_w1  = (const float*)d_in[12];
    const float* v2_b1  = (const float*)d_in[13];
    const float* v2_w2  = (const float*)d_in[14];
    const float* v2_b2  = (const float*)d_in[15];
    float* out = (float*)d_out;

    float *hA, *hB, *sum, *cnt;
    cudaGetSymbolAddress((void**)&hA, g_hA);
    cudaGetSymbolAddress((void**)&hB, g_hB);
    cudaGetSymbolAddress((void**)&sum, g_sum);
    cudaGetSymbolAddress((void**)&cnt, g_cnt);

    const int hab_smem  = HAB_SMEM_FLOATS * 4;
    const int edge_smem = EDGE_SMEM_FLOATS * 4;
    const int node_smem = NODE_SMEM_FLOATS * 4;
    cudaFuncSetAttribute(hab_kernel, cudaFuncAttributeMaxDynamicSharedMemorySize, hab_smem);
    cudaFuncSetAttribute(edge_kernel, cudaFuncAttributeMaxDynamicSharedMemorySize, edge_smem);
    cudaFuncSetAttribute(node_kernel, cudaFuncAttributeMaxDynamicSharedMemorySize, node_smem);

    cudaMemsetAsync(sum, 0, (size_t)N_NODES * HID * sizeof(float));
    cudaMemsetAsync(cnt, 0, (size_t)N_NODES * sizeof(float));

    const int node_blocks = (N_NODES + 31) / 32;  // 1563
    hab_kernel<<<node_blocks, 128, hab_smem>>>(h, e_w1, hA, hB);
    edge_kernel<<<592, 256, edge_smem>>>(hA, hB, eidx, eidx + N_EDGES, eattr,
                                         e_w1, e_b1, e_w2, e_b2, sum, cnt);
    node_kernel<<<node_blocks, 128, node_smem>>>(sum, cnt,
                                                 v1_w1, v1_b1, v1_w2, v1_b2,
                                                 v2_w1, v2_b1, v2_w2, v2_b2, out);
}

// round 6
// speedup vs baseline: 1.4260x; 1.4260x over previous
#include <cuda_runtime.h>
#include <math.h>

#define N_NODES 50000
#define N_EDGES 800000
#define HID 128
#define ANF 32
#define EPSV 1e-12f

typedef unsigned long long ull;

// -------- scratch (no allocations allowed; device globals) --------
__device__ float g_hA[N_NODES * HID];    // h @ e_w1[0:128,:]
__device__ float g_hB[N_NODES * HID];    // h @ e_w1[128:256,:]
__device__ float g_sum[N_NODES * HID];   // scatter-sum accumulator
__device__ float g_cnt[N_NODES];         // edge counts (float)

// -------- packed f32x2 helpers (FFMA2 is PTX-only) --------
__device__ __forceinline__ ull pack2(float x, float y) {
    ull r;
    asm("mov.b64 %0,{%1,%2};" : "=l"(r) : "r"(__float_as_uint(x)), "r"(__float_as_uint(y)));
    return r;
}
__device__ __forceinline__ ull dup2(float x) {
    ull r;
    asm("mov.b64 %0,{%1,%1};" : "=l"(r) : "r"(__float_as_uint(x)));
    return r;
}
__device__ __forceinline__ float2 unpack2(ull v) {
    unsigned a, b;
    asm("mov.b64 {%0,%1},%2;" : "=r"(a), "=r"(b) : "l"(v));
    return make_float2(__uint_as_float(a), __uint_as_float(b));
}
__device__ __forceinline__ ull fma2(ull a, ull b, ull c) {
    ull d;
    asm("fma.rn.f32x2 %0,%1,%2,%3;" : "=l"(d) : "l"(a), "l"(b), "l"(c));
    return d;
}
__device__ __forceinline__ float silu(float x) { return x / (1.0f + __expf(-x)); }

#define WSTR 132   // transposed-weight smem row stride (float4-aligned, conflict-free)

// ============================================================================
// Kernel 1: hA = h @ W1a, hB = h @ W1b.
// 256 threads = 256 output columns (t<128 -> A, t>=128 -> B), 8 nodes/pass.
// Weights transposed in smem [t][k] stride 132 -> LDS.128 per 4 k.
// ============================================================================
#define HAB_SMEM_FLOATS (256 * WSTR + HID * 8)
__global__ void __launch_bounds__(256, 1)
hab_kernel(const float* __restrict__ h,
           const float* __restrict__ e_w1,
           float* __restrict__ hA, float* __restrict__ hB) {
    extern __shared__ float s[];
    float* wT = s;                 // 256*132  [t][k]
    float* hq = wT + 256 * WSTR;   // 128*8    [k][m] pairs
    const int tid = threadIdx.x;
    const int tl = tid & 127;

    // wT[(half*128+tl)][k] = e_w1[(k + half*128)*128 + tl]
    for (int i = tid; i < 2 * HID * HID; i += 256) {
        const int tt = i & 127, kk = (i >> 7) & 127, half = i >> 14;
        wT[(half * HID + tt) * WSTR + kk] = e_w1[(kk + half * HID) * HID + tt];
    }
    __syncthreads();

    float* dst = (tid < HID) ? hA : hB;
    const int ngroups = N_NODES / 8;  // 6250, exact
    for (int g = blockIdx.x; g < ngroups; g += gridDim.x) {
        const int nb = g * 8;
        // hq[k][m] = h[(nb+m)*HID + k]; m fastest in idx -> conflict-free STS
        for (int idx = tid; idx < HID * 8; idx += 256) {
            const int m = idx & 7, k = idx >> 3;
            hq[k * 8 + m] = h[(nb + m) * HID + k];
        }
        __syncthreads();

        ull a01 = 0ull, a23 = 0ull, a45 = 0ull, a67 = 0ull;
#pragma unroll 8
        for (int k = 0; k < HID; k += 4) {
            const float4 wv = *(const float4*)&wT[tid * WSTR + k];
#pragma unroll
            for (int j = 0; j < 4; j++) {
                const float wj = j == 0 ? wv.x : j == 1 ? wv.y : j == 2 ? wv.z : wv.w;
                const ull wp = dup2(wj);
                const ulonglong2* hp = (const ulonglong2*)&hq[(k + j) * 8];
                const ulonglong2 h0 = hp[0], h1 = hp[1];
                a01 = fma2(h0.x, wp, a01);
                a23 = fma2(h0.y, wp, a23);
                a45 = fma2(h1.x, wp, a45);
                a67 = fma2(h1.y, wp, a67);
            }
        }
        float2 f;
        f = unpack2(a01); dst[(nb + 0) * HID + tl] = f.x; dst[(nb + 1) * HID + tl] = f.y;
        f = unpack2(a23); dst[(nb + 2) * HID + tl] = f.x; dst[(nb + 3) * HID + tl] = f.y;
        f = unpack2(a45); dst[(nb + 4) * HID + tl] = f.x; dst[(nb + 5) * HID + tl] = f.y;
        f = unpack2(a67); dst[(nb + 6) * HID + tl] = f.x; dst[(nb + 7) * HID + tl] = f.y;
        __syncthreads();
    }
}

// ============================================================================
// Kernel 2: edge MLP + scatter. 256 threads, 16 edges/group (2 halves x 8).
// pre = hA[row] + hB[col] + b1 + attr @ W1c ; ef1 = silu(pre)
// out = silu(ef1 @ W2 + b2) -> atomic scatter into g_sum[row]; count rows.
// W2/W1c transposed in smem; activations read as ulonglong2 pairs.
// ============================================================================
#define EG 16
#define EH 8
#define ESTR 20   // ef1t/attr row stride (16B-aligned pair reads, low-conflict writes)
#define W1CSTR 36
#define EDGE_SMEM_FLOATS (HID * WSTR + HID * W1CSTR + 128 + 128 + ANF * ESTR + HID * ESTR + 32)
__global__ void __launch_bounds__(256, 2)
edge_kernel(const float* __restrict__ hA, const float* __restrict__ hB,
            const int* __restrict__ row_idx, const int* __restrict__ col_idx,
            const float* __restrict__ edge_attr,
            const float* __restrict__ e_w1,   // W1c at rows 256..287
            const float* __restrict__ e_b1,
            const float* __restrict__ e_w2,
            const float* __restrict__ e_b2,
            float* __restrict__ gsum, float* __restrict__ gcnt) {
    extern __shared__ float s[];
    float* w2T    = s;                      // 128*132 [t][k]
    float* w1cT   = w2T + HID * WSTR;       // 128*36  [t][k]
    float* b1     = w1cT + HID * W1CSTR;    // 128
    float* b2     = b1 + 128;               // 128
    float* attr_t = b2 + 128;               // 32*20   [k][e]
    float* ef1t   = attr_t + ANF * ESTR;    // 128*20  [k][e]
    int*   rows   = (int*)(ef1t + HID * ESTR);  // 16
    int*   cols   = rows + EG;                  // 16
    const int tid = threadIdx.x;
    const int t   = tid & 127;   // feature
    const int eh  = tid >> 7;    // edge-half

    for (int i = tid; i < HID * HID; i += 256) {
        const int tt = i & 127, kk = i >> 7;
        w2T[tt * WSTR + kk] = e_w2[kk * HID + tt];
    }
    for (int i = tid; i < ANF * HID; i += 256) {
        const int tt = i & 127, kk = i >> 7;
        w1cT[tt * W1CSTR + kk] = e_w1[2 * HID * HID + kk * HID + tt];
    }
    if (tid < 128) { b1[tid] = e_b1[tid]; b2[tid] = e_b2[tid]; }
    __syncthreads();

    const float bb = b1[t];
    const float b2v = b2[t];
    const int ngroups = N_EDGES / EG;  // 50000, exact
    for (int g = blockIdx.x; g < ngroups; g += gridDim.x) {
        const int e0 = g * EG;
        if (tid < EG) {
            rows[tid] = row_idx[e0 + tid];
            cols[tid] = col_idx[e0 + tid];
        }
        for (int idx = tid; idx < EG * ANF; idx += 256) {
            const int e = idx & 15, k = idx >> 4;
            attr_t[k * ESTR + e] = edge_attr[(e0 + e) * ANF + k];
        }
        __syncthreads();

        if (tid < EG) atomicAdd(&gcnt[rows[tid]], 1.0f);

        // cache this half's indices in registers (lets us drop end-of-loop sync)
        int myrows[EH], mycols[EH];
#pragma unroll
        for (int e = 0; e < EH; e++) {
            myrows[e] = rows[eh * EH + e];
            mycols[e] = cols[eh * EH + e];
        }

        // -------- layer 1 --------
        float pre[EH];
#pragma unroll
        for (int e = 0; e < EH; e++) {
            pre[e] = hA[myrows[e] * HID + t] + hB[mycols[e] * HID + t] + bb;
        }
        ull p01 = pack2(pre[0], pre[1]);
        ull p23 = pack2(pre[2], pre[3]);
        ull p45 = pack2(pre[4], pre[5]);
        ull p67 = pack2(pre[6], pre[7]);
#pragma unroll
        for (int k = 0; k < ANF; k += 4) {
            const float4 wv = *(const float4*)&w1cT[t * W1CSTR + k];
#pragma unroll
            for (int j = 0; j < 4; j++) {
                const float wj = j == 0 ? wv.x : j == 1 ? wv.y : j == 2 ? wv.z : wv.w;
                const ull wp = dup2(wj);
                const ulonglong2* ap = (const ulonglong2*)&attr_t[(k + j) * ESTR + eh * EH];
                const ulonglong2 a0 = ap[0];
                p01 = fma2(a0.x, wp, p01);
                p23 = fma2(a0.y, wp, p23);
                const ull* ap1 = (const ull*)ap;
                p45 = fma2(ap1[2], wp, p45);
                p67 = fma2(ap1[3], wp, p67);
            }
        }
        {
            const float2 t0 = unpack2(p01), t1 = unpack2(p23);
            const float2 t2 = unpack2(p45), t3 = unpack2(p67);
            *(float4*)&ef1t[t * ESTR + eh * EH] =
                make_float4(silu(t0.x), silu(t0.y), silu(t1.x), silu(t1.y));
            *(float4*)&ef1t[t * ESTR + eh * EH + 4] =
                make_float4(silu(t2.x), silu(t2.y), silu(t3.x), silu(t3.y));
        }
        __syncthreads();

        // -------- layer 2 --------
        ull acc01 = dup2(b2v);
        ull acc23 = acc01, acc45 = acc01, acc67 = acc01;
#pragma unroll 8
        for (int k = 0; k < HID; k += 4) {
            const float4 wv = *(const float4*)&w2T[t * WSTR + k];
#pragma unroll
            for (int j = 0; j < 4; j++) {
                const float wj = j == 0 ? wv.x : j == 1 ? wv.y : j == 2 ? wv.z : wv.w;
                const ull wp = dup2(wj);
                const ulonglong2* qp = (const ulonglong2*)&ef1t[(k + j) * ESTR + eh * EH];
                const ulonglong2 q0 = qp[0], q1 = qp[1];
                acc01 = fma2(q0.x, wp, acc01);
                acc23 = fma2(q0.y, wp, acc23);
                acc45 = fma2(q1.x, wp, acc45);
                acc67 = fma2(q1.y, wp, acc67);
            }
        }
        {
            const float2 o0 = unpack2(acc01), o1 = unpack2(acc23);
            const float2 o2 = unpack2(acc45), o3 = unpack2(acc67);
            const float ov[EH] = {o0.x, o0.y, o1.x, o1.y, o2.x, o2.y, o3.x, o3.y};
#pragma unroll
            for (int e = 0; e < EH; e++) {
                atomicAdd(&gsum[myrows[e] * HID + t], silu(ov[e]));
            }
        }
        __syncthreads();  // protects ef1t (next group's layer-1 writes) — rows/cols/attr are reg/dbl-covered
    }
}

// ============================================================================
// Kernel 3: scatter-mean + two node MLPs + normalize/Gram-Schmidt/cross.
// 256 threads: t<128 -> branch1 hidden col, t>=128 -> branch2. 8 nodes/pass.
// ============================================================================
#define HSTRIDE 129
#define NODE_SMEM_FLOATS (256 * WSTR + HID * 8 + 16 * HSTRIDE + 2 * 384 + 256 + 8 + 48)
__global__ void __launch_bounds__(256, 1)
node_kernel(const float* __restrict__ gsum, const float* __restrict__ gcnt,
            const float* __restrict__ v1_w1, const float* __restrict__ v1_b1,
            const float* __restrict__ v1_w2, const float* __restrict__ v1_b2,
            const float* __restrict__ v2_w1, const float* __restrict__ v2_b1,
            const float* __restrict__ v2_w2, const float* __restrict__ v2_b2,
            float* __restrict__ out) {
    extern __shared__ float s[];
    float* wT   = s;                     // 256*132 [t][k]  (t<128: v1_w1, else v2_w1)
    float* nq   = wT + 256 * WSTR;       // 128*8   [k][m]
    float* hid  = nq + HID * 8;          // 16*129  [(m*2+br)][tl]
    float* w2a  = hid + 16 * HSTRIDE;    // 384
    float* w2b  = w2a + 384;             // 384
    float* sb   = w2b + 384;             // 256  per-thread layer1 bias
    float* b2ab = sb + 256;              // 8    [br*4+j]
    float* vecs = b2ab + 8;              // 48   [m*6 + br*3 + j]
    const int tid = threadIdx.x;
    const int tl = tid & 127;

    for (int i = tid; i < HID * HID; i += 256) {
        const int tt = i & 127, kk = i >> 7;
        wT[tt * WSTR + kk] = v1_w1[kk * HID + tt];
        wT[(HID + tt) * WSTR + kk] = v2_w1[kk * HID + tt];
    }
    for (int i = tid; i < 384; i += 256) { w2a[i] = v1_w2[i]; w2b[i] = v2_w2[i]; }
    if (tid < 128) { sb[tid] = v1_b1[tid]; sb[tid + 128] = v2_b1[tid]; }
    if (tid < 3)   { b2ab[tid] = v1_b2[tid]; b2ab[4 + tid] = v2_b2[tid]; }
    __syncthreads();

    const float myb = sb[tid];
    const int ngroups = N_NODES / 8;  // 6250, exact
    for (int g = blockIdx.x; g < ngroups; g += gridDim.x) {
        const int nb = g * 8;
        for (int idx = tid; idx < HID * 8; idx += 256) {
            const int m = idx & 7, k = idx >> 3;
            const int n = nb + m;
            nq[k * 8 + m] = gsum[n * HID + k] / fmaxf(gcnt[n], 1.0f);
        }
        __syncthreads();

        ull a01 = dup2(myb);
        ull a23 = a01, a45 = a01, a67 = a01;
#pragma unroll 8
        for (int k = 0; k < HID; k += 4) {
            const float4 wv = *(const float4*)&wT[tid * WSTR + k];
#pragma unroll
            for (int j = 0; j < 4; j++) {
                const float wj = j == 0 ? wv.x : j == 1 ? wv.y : j == 2 ? wv.z : wv.w;
                const ull wp = dup2(wj);
                const ulonglong2* hp = (const ulonglong2*)&nq[(k + j) * 8];
                const ulonglong2 h0 = hp[0], h1 = hp[1];
                a01 = fma2(h0.x, wp, a01);
                a23 = fma2(h0.y, wp, a23);
                a45 = fma2(h1.x, wp, a45);
                a67 = fma2(h1.y, wp, a67);
            }
        }
        {
            const int br = tid >> 7;
            float2 f;
            f = unpack2(a01);
            hid[(0 * 2 + br) * HSTRIDE + tl] = silu(f.x);
            hid[(1 * 2 + br) * HSTRIDE + tl] = silu(f.y);
            f = unpack2(a23);
            hid[(2 * 2 + br) * HSTRIDE + tl] = silu(f.x);
            hid[(3 * 2 + br) * HSTRIDE + tl] = silu(f.y);
            f = unpack2(a45);
            hid[(4 * 2 + br) * HSTRIDE + tl] = silu(f.x);
            hid[(5 * 2 + br) * HSTRIDE + tl] = silu(f.y);
            f = unpack2(a67);
            hid[(6 * 2 + br) * HSTRIDE + tl] = silu(f.x);
            hid[(7 * 2 + br) * HSTRIDE + tl] = silu(f.y);
        }
        __syncthreads();

        if (tid < 48) {
            const int m = tid / 6, r = tid % 6, br = r / 3, j = r % 3;
            const float* hh = &hid[(m * 2 + br) * HSTRIDE];
            const float* ww = br ? w2b : w2a;
            float acc = b2ab[br * 4 + j];
#pragma unroll 8
            for (int tt = 0; tt < HID; tt++) acc += hh[tt] * ww[tt * 3 + j];
            vecs[m * 6 + r] = acc;
        }
        __syncthreads();

        if (tid < 8) {
            const float* v = &vecs[tid * 6];
            float v1x = v[0], v1y = v[1], v1z = v[2];
            float v2x = v[3], v2y = v[4], v2z = v[5];
            float n1 = fmaxf(sqrtf(v1x * v1x + v1y * v1y + v1z * v1z), EPSV);
            v1x /= n1; v1y /= n1; v1z /= n1;
            const float d = v2x * v1x + v2y * v1y + v2z * v1z;
            v2x -= d * v1x; v2y -= d * v1y; v2z -= d * v1z;
            float n2 = fmaxf(sqrtf(v2x * v2x + v2y * v2y + v2z * v2z), EPSV);
            v2x /= n2; v2y /= n2; v2z /= n2;
            const float cx = v1y * v2z - v1z * v2y;
            const float cy = v1z * v2x - v1x * v2z;
            const float cz = v1x * v2y - v1y * v2x;
            float* o = &out[(size_t)(nb + tid) * 9];
            o[0] = v1x; o[1] = v2x; o[2] = cx;
            o[3] = v1y; o[4] = v2y; o[5] = cy;
            o[6] = v1z; o[7] = v2z; o[8] = cz;
        }
        __syncthreads();
    }
}

// ============================================================================
// Launch
// ============================================================================
extern "C" void kernel_launch(void* const* d_in, const int* in_sizes, int n_in,
                              void* d_out, int out_size) {
    const float* h      = (const float*)d_in[0];
    // d_in[1] = x (unused by reference)
    const int*   eidx   = (const int*)d_in[2];
    const float* eattr  = (const float*)d_in[3];
    const float* e_w1   = (const float*)d_in[4];
    const float* e_b1   = (const float*)d_in[5];
    const float* e_w2   = (const float*)d_in[6];
    const float* e_b2   = (const float*)d_in[7];
    const float* v1_w1  = (const float*)d_in[8];
    const float* v1_b1  = (const float*)d_in[9];
    const float* v1_w2  = (const float*)d_in[10];
    const float* v1_b2  = (const float*)d_in[11];
    const float* v2_w1  = (const float*)d_in[12];
    const float* v2_b1  = (const float*)d_in[13];
    const float* v2_w2  = (const float*)d_in[14];
    const float* v2_b2  = (const float*)d_in[15];
    float* out = (float*)d_out;

    float *hA, *hB, *sum, *cnt;
    cudaGetSymbolAddress((void**)&hA, g_hA);
    cudaGetSymbolAddress((void**)&hB, g_hB);
    cudaGetSymbolAddress((void**)&sum, g_sum);
    cudaGetSymbolAddress((void**)&cnt, g_cnt);

    const int hab_smem  = HAB_SMEM_FLOATS * 4;
    const int edge_smem = EDGE_SMEM_FLOATS * 4;
    const int node_smem = NODE_SMEM_FLOATS * 4;
    cudaFuncSetAttribute(hab_kernel, cudaFuncAttributeMaxDynamicSharedMemorySize, hab_smem);
    cudaFuncSetAttribute(edge_kernel, cudaFuncAttributeMaxDynamicSharedMemorySize, edge_smem);
    cudaFuncSetAttribute(node_kernel, cudaFuncAttributeMaxDynamicSharedMemorySize, node_smem);

    cudaMemsetAsync(sum, 0, (size_t)N_NODES * HID * sizeof(float));
    cudaMemsetAsync(cnt, 0, (size_t)N_NODES * sizeof(float));

    hab_kernel<<<148, 256, hab_smem>>>(h, e_w1, hA, hB);
    edge_kernel<<<296, 256, edge_smem>>>(hA, hB, eidx, eidx + N_EDGES, eattr,
                                         e_w1, e_b1, e_w2, e_b2, sum, cnt);
    node_kernel<<<148, 256, node_smem>>>(sum, cnt,
                                         v1_w1, v1_b1, v1_w2, v1_b2,
                                         v2_w1, v2_b1, v2_w2, v2_b2, out);
}

// round 7
// speedup vs baseline: 1.5784x; 1.1069x over previous
#include <cuda_runtime.h>
#include <math.h>

#define N_NODES 50000
#define N_EDGES 800000
#define HID 128
#define ANF 32
#define EPSV 1e-12f

typedef unsigned long long ull;

// -------- scratch (no allocations allowed; device globals) --------
__device__ float g_hA[N_NODES * HID];
__device__ float g_hB[N_NODES * HID];
__device__ float g_sum[N_NODES * HID];
__device__ float g_cnt[N_NODES];

// -------- packed f32x2 helpers (FFMA2 is PTX-only) --------
__device__ __forceinline__ ull pack2(float x, float y) {
    ull r;
    asm("mov.b64 %0,{%1,%2};" : "=l"(r) : "r"(__float_as_uint(x)), "r"(__float_as_uint(y)));
    return r;
}
__device__ __forceinline__ ull dup2(float x) {
    ull r;
    asm("mov.b64 %0,{%1,%1};" : "=l"(r) : "r"(__float_as_uint(x)));
    return r;
}
__device__ __forceinline__ float2 unpack2(ull v) {
    unsigned a, b;
    asm("mov.b64 {%0,%1},%2;" : "=r"(a), "=r"(b) : "l"(v));
    return make_float2(__uint_as_float(a), __uint_as_float(b));
}
__device__ __forceinline__ ull fma2(ull a, ull b, ull c) {
    ull d;
    asm("fma.rn.f32x2 %0,%1,%2,%3;" : "=l"(d) : "l"(a), "l"(b), "l"(c));
    return d;
}
__device__ __forceinline__ void red_add_v4(float* p, float4 v) {
    asm volatile("red.global.add.v4.f32 [%0], {%1,%2,%3,%4};"
                 :: "l"(p), "f"(v.x), "f"(v.y), "f"(v.z), "f"(v.w) : "memory");
}
__device__ __forceinline__ float silu(float x) { return x / (1.0f + __expf(-x)); }

#define WSTR 132   // transposed-weight row stride (16B-aligned, low-conflict)
#define HQS  20    // activation-tile row stride (16B-aligned, 4-way max)

// ============================================================================
// Kernel 1: hA = h @ W1a, hB = h @ W1b.  256 threads = 256 output cols,
// 16 nodes per pass.  Per 4k: 1 LDS.128 weight + 16 LDS.128 act + 32 FFMA2.
// ============================================================================
#define HAB_SMEM_FLOATS (256 * WSTR + HID * HQS)
__global__ void __launch_bounds__(256, 1)
hab_kernel(const float* __restrict__ h,
           const float* __restrict__ e_w1,
           float* __restrict__ hA, float* __restrict__ hB) {
    extern __shared__ float s[];
    float* wT = s;                 // 256*132 [t][k]
    float* hq = wT + 256 * WSTR;   // 128*20  [k][m], m<16
    const int tid = threadIdx.x;
    const int tl = tid & 127;

    for (int i = tid; i < 2 * HID * HID; i += 256) {
        const int tt = i & 127, kk = (i >> 7) & 127, half = i >> 14;
        wT[(half * HID + tt) * WSTR + kk] = e_w1[(kk + half * HID) * HID + tt];
    }
    __syncthreads();

    float* dst = (tid < HID) ? hA : hB;
    const int ngroups = N_NODES / 16;  // 3125
    for (int g = blockIdx.x; g < ngroups; g += gridDim.x) {
        const int nb = g * 16;
        // coalesced gmem read, transposed STS
        for (int idx = tid; idx < 16 * HID; idx += 256) {
            const float v = h[nb * HID + idx];
            const int m = idx >> 7, k = idx & 127;
            hq[k * HQS + m] = v;
        }
        __syncthreads();

        ull a[8];
#pragma unroll
        for (int i = 0; i < 8; i++) a[i] = 0ull;
#pragma unroll 4
        for (int k = 0; k < HID; k += 4) {
            const float4 wv = *(const float4*)&wT[tid * WSTR + k];
#pragma unroll
            for (int j = 0; j < 4; j++) {
                const float wj = j == 0 ? wv.x : j == 1 ? wv.y : j == 2 ? wv.z : wv.w;
                const ull wp = dup2(wj);
                const ulonglong2* hp = (const ulonglong2*)&hq[(k + j) * HQS];
                const ulonglong2 q0 = hp[0], q1 = hp[1], q2 = hp[2], q3 = hp[3];
                a[0] = fma2(q0.x, wp, a[0]); a[1] = fma2(q0.y, wp, a[1]);
                a[2] = fma2(q1.x, wp, a[2]); a[3] = fma2(q1.y, wp, a[3]);
                a[4] = fma2(q2.x, wp, a[4]); a[5] = fma2(q2.y, wp, a[5]);
                a[6] = fma2(q3.x, wp, a[6]); a[7] = fma2(q3.y, wp, a[7]);
            }
        }
#pragma unroll
        for (int i = 0; i < 8; i++) {
            const float2 f = unpack2(a[i]);
            dst[(nb + 2 * i + 0) * HID + tl] = f.x;
            dst[(nb + 2 * i + 1) * HID + tl] = f.y;
        }
        __syncthreads();
    }
}

// ============================================================================
// Kernel 2: edge MLP + scatter. 256 threads, 32 edges/group (2 halves x 16).
// Epilogue: transpose through smem (reusing ef1 buffer) -> red.global.add.v4.
// ============================================================================
#define EG 32
#define EH 16
#define ESTR 36    // attr/ef1 row stride
#define OSTR 132   // epilogue transpose row stride
#define EDGE_SMEM_FLOATS (HID * WSTR + HID * ESTR + 128 + 128 + ANF * ESTR + HID * ESTR + 40)
__global__ void __launch_bounds__(256, 2)
edge_kernel(const float* __restrict__ hA, const float* __restrict__ hB,
            const int* __restrict__ row_idx, const int* __restrict__ col_idx,
            const float* __restrict__ edge_attr,
            const float* __restrict__ e_w1,   // W1c at rows 256..287
            const float* __restrict__ e_b1,
            const float* __restrict__ e_w2,
            const float* __restrict__ e_b2,
            float* __restrict__ gsum, float* __restrict__ gcnt) {
    extern __shared__ float s[];
    float* w2T    = s;                      // 128*132 [t][k]
    float* w1cT   = w2T + HID * WSTR;       // 128*36  [t][k]
    float* b1     = w1cT + HID * ESTR;      // 128
    float* b2     = b1 + 128;               // 128
    float* attr_t = b2 + 128;               // 32*36   [k][e]
    float* ef1t   = attr_t + ANF * ESTR;    // 128*36  [k][e]; reused as ot[32][132]
    int*   rows   = (int*)(ef1t + HID * ESTR);  // 32
    const int tid = threadIdx.x;
    const int t   = tid & 127;   // feature
    const int eh  = tid >> 7;    // edge-half

    for (int i = tid; i < HID * HID; i += 256) {
        const int tt = i & 127, kk = i >> 7;
        w2T[tt * WSTR + kk] = e_w2[kk * HID + tt];
    }
    for (int i = tid; i < ANF * HID; i += 256) {
        const int tt = i & 127, kk = i >> 7;
        w1cT[tt * ESTR + kk] = e_w1[2 * HID * HID + kk * HID + tt];
    }
    if (tid < 128) { b1[tid] = e_b1[tid]; b2[tid] = e_b2[tid]; }
    __syncthreads();

    const float bb = b1[t];
    const float b2v = b2[t];
    float* ot = ef1t;  // reuse
    const int ngroups = N_EDGES / EG;  // 25000
    for (int g = blockIdx.x; g < ngroups; g += gridDim.x) {
        const int e0 = g * EG;
        int mycols[EH];
        if (tid < EG) rows[tid] = row_idx[e0 + tid];
        // coalesced attr read, transposed STS
        for (int idx = tid; idx < EG * ANF; idx += 256) {
            const float v = edge_attr[e0 * ANF + idx];
            const int e = idx >> 5, k = idx & 31;
            attr_t[k * ESTR + e] = v;
        }
#pragma unroll
        for (int e = 0; e < EH; e++) mycols[e] = col_idx[e0 + eh * EH + e];
        __syncthreads();                                            // (a)

        if (tid < EG) atomicAdd(&gcnt[rows[tid]], 1.0f);
        int myrows[EH], redrows[4];
#pragma unroll
        for (int e = 0; e < EH; e++) myrows[e] = rows[eh * EH + e];
#pragma unroll
        for (int r = 0; r < 4; r++) redrows[r] = rows[((r << 8) + tid) >> 5];

        // -------- layer 1 --------
        ull p[8];
#pragma unroll
        for (int e = 0; e < EH; e += 2) {
            const float x0 = hA[myrows[e] * HID + t] + hB[mycols[e] * HID + t] + bb;
            const float x1 = hA[myrows[e + 1] * HID + t] + hB[mycols[e + 1] * HID + t] + bb;
            p[e >> 1] = pack2(x0, x1);
        }
#pragma unroll 4
        for (int k = 0; k < ANF; k += 4) {
            const float4 wv = *(const float4*)&w1cT[t * ESTR + k];
#pragma unroll
            for (int j = 0; j < 4; j++) {
                const float wj = j == 0 ? wv.x : j == 1 ? wv.y : j == 2 ? wv.z : wv.w;
                const ull wp = dup2(wj);
                const ulonglong2* ap = (const ulonglong2*)&attr_t[(k + j) * ESTR + eh * EH];
                const ulonglong2 q0 = ap[0], q1 = ap[1], q2 = ap[2], q3 = ap[3];
                p[0] = fma2(q0.x, wp, p[0]); p[1] = fma2(q0.y, wp, p[1]);
                p[2] = fma2(q1.x, wp, p[2]); p[3] = fma2(q1.y, wp, p[3]);
                p[4] = fma2(q2.x, wp, p[4]); p[5] = fma2(q2.y, wp, p[5]);
                p[6] = fma2(q3.x, wp, p[6]); p[7] = fma2(q3.y, wp, p[7]);
            }
        }
#pragma unroll
        for (int i = 0; i < 8; i += 2) {
            const float2 f0 = unpack2(p[i]), f1 = unpack2(p[i + 1]);
            *(float4*)&ef1t[t * ESTR + eh * EH + 2 * i] =
                make_float4(silu(f0.x), silu(f0.y), silu(f1.x), silu(f1.y));
        }
        __syncthreads();                                            // (b)

        // -------- layer 2 --------
        ull c[8];
#pragma unroll
        for (int i = 0; i < 8; i++) c[i] = dup2(b2v);
#pragma unroll 4
        for (int k = 0; k < HID; k += 4) {
            const float4 wv = *(const float4*)&w2T[t * WSTR + k];
#pragma unroll
            for (int j = 0; j < 4; j++) {
                const float wj = j == 0 ? wv.x : j == 1 ? wv.y : j == 2 ? wv.z : wv.w;
                const ull wp = dup2(wj);
                const ulonglong2* qp = (const ulonglong2*)&ef1t[(k + j) * ESTR + eh * EH];
                const ulonglong2 q0 = qp[0], q1 = qp[1], q2 = qp[2], q3 = qp[3];
                c[0] = fma2(q0.x, wp, c[0]); c[1] = fma2(q0.y, wp, c[1]);
                c[2] = fma2(q1.x, wp, c[2]); c[3] = fma2(q1.y, wp, c[3]);
                c[4] = fma2(q2.x, wp, c[4]); c[5] = fma2(q2.y, wp, c[5]);
                c[6] = fma2(q3.x, wp, c[6]); c[7] = fma2(q3.y, wp, c[7]);
            }
        }
        float sv[EH];
#pragma unroll
        for (int i = 0; i < 8; i++) {
            const float2 f = unpack2(c[i]);
            sv[2 * i] = silu(f.x);
            sv[2 * i + 1] = silu(f.y);
        }
        __syncthreads();                                            // (c) ef1t reads done

        // transpose: ot[e][t]
#pragma unroll
        for (int e = 0; e < EH; e++) ot[(eh * EH + e) * OSTR + t] = sv[e];
        __syncthreads();                                            // (d)

        // vector scatter: each thread does 4 x red.v4 (one edge, 4 features)
#pragma unroll
        for (int r = 0; r < 4; r++) {
            const int idx = (r << 8) + tid;
            const int e = idx >> 5, fg = idx & 31;
            const float4 v = *(const float4*)&ot[e * OSTR + 4 * fg];
            red_add_v4(&gsum[redrows[r] * HID + 4 * fg], v);
        }
        // no trailing sync: next iter's smem writes are ordered by (a)
    }
}

// ============================================================================
// Kernel 3: scatter-mean + node MLPs + normalize/Gram-Schmidt/cross.
// 256 threads (t<128 branch1, else branch2), 16 nodes per pass.
// ============================================================================
#define HSTRIDE 129
#define NODE_SMEM_FLOATS (256 * WSTR + HID * HQS + 32 * HSTRIDE + 2 * 384 + 256 + 8 + 96)
__global__ void __launch_bounds__(256, 1)
node_kernel(const float* __restrict__ gsum, const float* __restrict__ gcnt,
            const float* __restrict__ v1_w1, const float* __restrict__ v1_b1,
            const float* __restrict__ v1_w2, const float* __restrict__ v1_b2,
            const float* __restrict__ v2_w1, const float* __restrict__ v2_b1,
            const float* __restrict__ v2_w2, const float* __restrict__ v2_b2,
            float* __restrict__ out) {
    extern __shared__ float s[];
    float* wT   = s;                     // 256*132
    float* nq   = wT + 256 * WSTR;       // 128*20 [k][m]
    float* hid  = nq + HID * HQS;        // 32*129 [(m*2+br)][tl]
    float* w2a  = hid + 32 * HSTRIDE;    // 384
    float* w2b  = w2a + 384;             // 384
    float* sb   = w2b + 384;             // 256
    float* b2ab = sb + 256;              // 8
    float* vecs = b2ab + 8;              // 96
    const int tid = threadIdx.x;
    const int tl = tid & 127;

    for (int i = tid; i < HID * HID; i += 256) {
        const int tt = i & 127, kk = i >> 7;
        wT[tt * WSTR + kk] = v1_w1[kk * HID + tt];
        wT[(HID + tt) * WSTR + kk] = v2_w1[kk * HID + tt];
    }
    for (int i = tid; i < 384; i += 256) { w2a[i] = v1_w2[i]; w2b[i] = v2_w2[i]; }
    if (tid < 128) { sb[tid] = v1_b1[tid]; sb[tid + 128] = v2_b1[tid]; }
    if (tid < 3)   { b2ab[tid] = v1_b2[tid]; b2ab[4 + tid] = v2_b2[tid]; }
    __syncthreads();

    const float myb = sb[tid];
    const int ngroups = N_NODES / 16;  // 3125
    for (int g = blockIdx.x; g < ngroups; g += gridDim.x) {
        const int nb = g * 16;
        for (int idx = tid; idx < 16 * HID; idx += 256) {
            const int m = idx >> 7, k = idx & 127;
            const float v = gsum[nb * HID + idx] / fmaxf(gcnt[nb + m], 1.0f);
            nq[k * HQS + m] = v;
        }
        __syncthreads();

        ull a[8];
#pragma unroll
        for (int i = 0; i < 8; i++) a[i] = dup2(myb);
#pragma unroll 4
        for (int k = 0; k < HID; k += 4) {
            const float4 wv = *(const float4*)&wT[tid * WSTR + k];
#pragma unroll
            for (int j = 0; j < 4; j++) {
                const float wj = j == 0 ? wv.x : j == 1 ? wv.y : j == 2 ? wv.z : wv.w;
                const ull wp = dup2(wj);
                const ulonglong2* hp = (const ulonglong2*)&nq[(k + j) * HQS];
                const ulonglong2 q0 = hp[0], q1 = hp[1], q2 = hp[2], q3 = hp[3];
                a[0] = fma2(q0.x, wp, a[0]); a[1] = fma2(q0.y, wp, a[1]);
                a[2] = fma2(q1.x, wp, a[2]); a[3] = fma2(q1.y, wp, a[3]);
                a[4] = fma2(q2.x, wp, a[4]); a[5] = fma2(q2.y, wp, a[5]);
                a[6] = fma2(q3.x, wp, a[6]); a[7] = fma2(q3.y, wp, a[7]);
            }
        }
        {
            const int br = tid >> 7;
#pragma unroll
            for (int i = 0; i < 8; i++) {
                const float2 f = unpack2(a[i]);
                hid[((2 * i + 0) * 2 + br) * HSTRIDE + tl] = silu(f.x);
                hid[((2 * i + 1) * 2 + br) * HSTRIDE + tl] = silu(f.y);
            }
        }
        __syncthreads();

        if (tid < 96) {
            const int m = tid / 6, r = tid % 6, br = r / 3, j = r % 3;
            const float* hh = &hid[(m * 2 + br) * HSTRIDE];
            const float* ww = br ? w2b : w2a;
            float acc = b2ab[br * 4 + j];
#pragma unroll 8
            for (int tt = 0; tt < HID; tt++) acc += hh[tt] * ww[tt * 3 + j];
            vecs[m * 6 + r] = acc;
        }
        __syncthreads();

        if (tid < 16) {
            const float* v = &vecs[tid * 6];
            float v1x = v[0], v1y = v[1], v1z = v[2];
            float v2x = v[3], v2y = v[4], v2z = v[5];
            float n1 = fmaxf(sqrtf(v1x * v1x + v1y * v1y + v1z * v1z), EPSV);
            v1x /= n1; v1y /= n1; v1z /= n1;
            const float d = v2x * v1x + v2y * v1y + v2z * v1z;
            v2x -= d * v1x; v2y -= d * v1y; v2z -= d * v1z;
            float n2 = fmaxf(sqrtf(v2x * v2x + v2y * v2y + v2z * v2z), EPSV);
            v2x /= n2; v2y /= n2; v2z /= n2;
            const float cx = v1y * v2z - v1z * v2y;
            const float cy = v1z * v2x - v1x * v2z;
            const float cz = v1x * v2y - v1y * v2x;
            float* o = &out[(size_t)(nb + tid) * 9];
            o[0] = v1x; o[1] = v2x; o[2] = cx;
            o[3] = v1y; o[4] = v2y; o[5] = cy;
            o[6] = v1z; o[7] = v2z; o[8] = cz;
        }
        __syncthreads();
    }
}

// ============================================================================
// Launch
// ============================================================================
extern "C" void kernel_launch(void* const* d_in, const int* in_sizes, int n_in,
                              void* d_out, int out_size) {
    const float* h      = (const float*)d_in[0];
    const int*   eidx   = (const int*)d_in[2];
    const float* eattr  = (const float*)d_in[3];
    const float* e_w1   = (const float*)d_in[4];
    const float* e_b1   = (const float*)d_in[5];
    const float* e_w2   = (const float*)d_in[6];
    const float* e_b2   = (const float*)d_in[7];
    const float* v1_w1  = (const float*)d_in[8];
    const float* v1_b1  = (const float*)d_in[9];
    const float* v1_w2  = (const float*)d_in[10];
    const float* v1_b2  = (const float*)d_in[11];
    const float* v2_w1  = (const float*)d_in[12];
    const float* v2_b1  = (const float*)d_in[13];
    const float* v2_w2  = (const float*)d_in[14];
    const float* v2_b2  = (const float*)d_in[15];
    float* out = (float*)d_out;

    float *hA, *hB, *sum, *cnt;
    cudaGetSymbolAddress((void**)&hA, g_hA);
    cudaGetSymbolAddress((void**)&hB, g_hB);
    cudaGetSymbolAddress((void**)&sum, g_sum);
    cudaGetSymbolAddress((void**)&cnt, g_cnt);

    const int hab_smem  = HAB_SMEM_FLOATS * 4;
    const int edge_smem = EDGE_SMEM_FLOATS * 4;
    const int node_smem = NODE_SMEM_FLOATS * 4;
    cudaFuncSetAttribute(hab_kernel, cudaFuncAttributeMaxDynamicSharedMemorySize, hab_smem);
    cudaFuncSetAttribute(edge_kernel, cudaFuncAttributeMaxDynamicSharedMemorySize, edge_smem);
    cudaFuncSetAttribute(node_kernel, cudaFuncAttributeMaxDynamicSharedMemorySize, node_smem);

    cudaMemsetAsync(sum, 0, (size_t)N_NODES * HID * sizeof(float));
    cudaMemsetAsync(cnt, 0, (size_t)N_NODES * sizeof(float));

    hab_kernel<<<148, 256, hab_smem>>>(h, e_w1, hA, hB);
    edge_kernel<<<296, 256, edge_smem>>>(hA, hB, eidx, eidx + N_EDGES, eattr,
                                         e_w1, e_b1, e_w2, e_b2, sum, cnt);
    node_kernel<<<148, 256, node_smem>>>(sum, cnt,
                                         v1_w1, v1_b1, v1_w2, v1_b2,
                                         v2_w1, v2_b1, v2_w2, v2_b2, out);
}

// round 8
// speedup vs baseline: 2.0432x; 1.2945x over previous
#include <cuda_runtime.h>
#include <math.h>

#define N_NODES 50000
#define N_EDGES 800000
#define HID 128
#define ANF 32
#define EPSV 1e-12f

typedef unsigned long long ull;

// -------- scratch --------
__device__ float g_hA[N_NODES * HID];
__device__ float g_hB[N_NODES * HID];
__device__ float g_sum[N_NODES * HID];
__device__ float g_cnt[N_NODES];

// -------- packed f32x2 helpers (FFMA2 is PTX-only) --------
__device__ __forceinline__ ull pack2(float x, float y) {
    ull r;
    asm("mov.b64 %0,{%1,%2};" : "=l"(r) : "r"(__float_as_uint(x)), "r"(__float_as_uint(y)));
    return r;
}
__device__ __forceinline__ ull dup2(float x) {
    ull r;
    asm("mov.b64 %0,{%1,%1};" : "=l"(r) : "r"(__float_as_uint(x)));
    return r;
}
__device__ __forceinline__ float2 unpack2(ull v) {
    unsigned a, b;
    asm("mov.b64 {%0,%1},%2;" : "=r"(a), "=r"(b) : "l"(v));
    return make_float2(__uint_as_float(a), __uint_as_float(b));
}
__device__ __forceinline__ ull fma2(ull a, ull b, ull c) {
    ull d;
    asm("fma.rn.f32x2 %0,%1,%2,%3;" : "=l"(d) : "l"(a), "l"(b), "l"(c));
    return d;
}
__device__ __forceinline__ void red_add_v4(float* p, float4 v) {
    asm volatile("red.global.add.v4.f32 [%0], {%1,%2,%3,%4};"
                 :: "l"(p), "f"(v.x), "f"(v.y), "f"(v.z), "f"(v.w) : "memory");
}
__device__ __forceinline__ float silu(float x) { return x / (1.0f + __expf(-x)); }

#define WSTR 132   // per-feature transposed-weight stride (≡4 mod 32: conflict-free LDS.128)
#define HQS  20    // activation-tile row stride

// ============================================================================
// Kernel 1: hA = h @ W1a, hB = h @ W1b.  512 threads (16 warps/SM):
// tid&255 -> output col (0-127 A, 128-255 B), tid>>8 -> node half (8 nodes).
// ============================================================================
#define HAB_SMEM_FLOATS (256 * WSTR + HID * HQS)
__global__ void __launch_bounds__(512, 1)
hab_kernel(const float* __restrict__ h,
           const float* __restrict__ e_w1,
           float* __restrict__ hA, float* __restrict__ hB) {
    extern __shared__ float s[];
    float* wT = s;                 // 256*132 [t][k]
    float* hq = wT + 256 * WSTR;   // 128*20  [k][m], m<16
    const int tid = threadIdx.x;
    const int tc = tid & 255;      // output column (A or B)
    const int tl = tid & 127;
    const int nh = tid >> 8;       // node half: 0 -> m 0..7, 1 -> m 8..15

    for (int i = tid; i < 2 * HID * HID; i += 512) {
        const int tt = i & 127, kk = (i >> 7) & 127, half = i >> 14;
        wT[(half * HID + tt) * WSTR + kk] = e_w1[(kk + half * HID) * HID + tt];
    }
    __syncthreads();

    float* dst = (tc < HID) ? hA : hB;
    const int ngroups = N_NODES / 16;  // 3125
    for (int g = blockIdx.x; g < ngroups; g += gridDim.x) {
        const int nb = g * 16;
        for (int idx = tid; idx < 16 * HID; idx += 512) {
            const float v = h[nb * HID + idx];
            const int m = idx >> 7, k = idx & 127;
            hq[k * HQS + m] = v;
        }
        __syncthreads();

        ull a[4];
#pragma unroll
        for (int i = 0; i < 4; i++) a[i] = 0ull;
#pragma unroll 4
        for (int k = 0; k < HID; k += 4) {
            const float4 wv = *(const float4*)&wT[tc * WSTR + k];
#pragma unroll
            for (int j = 0; j < 4; j++) {
                const float wj = j == 0 ? wv.x : j == 1 ? wv.y : j == 2 ? wv.z : wv.w;
                const ull wp = dup2(wj);
                const ulonglong2* hp = (const ulonglong2*)&hq[(k + j) * HQS + nh * 8];
                const ulonglong2 q0 = hp[0], q1 = hp[1];
                a[0] = fma2(q0.x, wp, a[0]); a[1] = fma2(q0.y, wp, a[1]);
                a[2] = fma2(q1.x, wp, a[2]); a[3] = fma2(q1.y, wp, a[3]);
            }
        }
#pragma unroll
        for (int i = 0; i < 4; i++) {
            const float2 f = unpack2(a[i]);
            dst[(nb + nh * 8 + 2 * i + 0) * HID + tl] = f.x;
            dst[(nb + nh * 8 + 2 * i + 1) * HID + tl] = f.y;
        }
        __syncthreads();
    }
}

// ============================================================================
// Kernel 2: edge MLP + scatter.  256 threads: fg = tid&31 (4 features),
// eslot = tid>>5 (4 edges); each thread owns a 4x4 output tile of a
// 32-edge group.  Weights interleaved [fg][k*4+c]; acts broadcast [k][e].
// Direct per-thread red.v4 epilogue (no transpose), 2 syncs/group.
// ============================================================================
#define EG 32
#define ASTR 36     // attr/ef1 row stride
#define W4STR 516   // interleaved layer2 weight row stride (fg-major)
#define W1STR 132   // interleaved layer1 weight row stride
#define EDGE_SMEM_FLOATS (32 * W4STR + 32 * W1STR + ANF * ASTR + HID * ASTR)
__global__ void __launch_bounds__(256, 2)
edge_kernel(const float* __restrict__ hA, const float* __restrict__ hB,
            const int* __restrict__ row_idx, const int* __restrict__ col_idx,
            const float* __restrict__ edge_attr,
            const float* __restrict__ e_w1,   // W1c at rows 256..287
            const float* __restrict__ e_b1,
            const float* __restrict__ e_w2,
            const float* __restrict__ e_b2,
            float* __restrict__ gsum, float* __restrict__ gcnt) {
    extern __shared__ float s[];
    float* w2T4   = s;                      // 32*516 [fg][k*4+c]
    float* w1cT4  = w2T4 + 32 * W4STR;      // 32*132 [fg][k*4+c]
    float* attr_t = w1cT4 + 32 * W1STR;     // 32*36  [k][e]
    float* ef1t   = attr_t + ANF * ASTR;    // 128*36 [k][e]
    const int tid = threadIdx.x;
    const int fg  = tid & 31;    // feature group (features 4fg..4fg+3)
    const int eslot = tid >> 5;  // edge slot (edges 4*eslot..+3)

    for (int i = tid; i < HID * HID; i += 256) {
        const int k = i >> 7, f = i & 127;
        w2T4[(f >> 2) * W4STR + (k << 2) + (f & 3)] = e_w2[i];
    }
    for (int i = tid; i < ANF * HID; i += 256) {
        const int k = i >> 7, f = i & 127;
        w1cT4[(f >> 2) * W1STR + (k << 2) + (f & 3)] = e_w1[2 * HID * HID + i];
    }
    const float4 b1v = *(const float4*)&e_b1[4 * fg];
    const float4 b2v = *(const float4*)&e_b2[4 * fg];
    __syncthreads();

    const int ngroups = N_EDGES / EG;  // 25000
    for (int g = blockIdx.x; g < ngroups; g += gridDim.x) {
        const int e0g = g * EG;
        int rowv[4], colv[4];
#pragma unroll
        for (int e = 0; e < 4; e++) {
            rowv[e] = row_idx[e0g + eslot * 4 + e];
            colv[e] = col_idx[e0g + eslot * 4 + e];
        }
        for (int idx = tid; idx < EG * ANF; idx += 256) {
            const float v = edge_attr[e0g * ANF + idx];
            const int e = idx >> 5, k = idx & 31;
            attr_t[k * ASTR + e] = v;
        }
        __syncthreads();                                            // (a)

        if (tid < EG) atomicAdd(&gcnt[rowv[0] * 0 + row_idx[e0g + tid]], 1.0f);

        // -------- layer 1: pre = hA[row] + hB[col] + b1 ; += attr @ W1c ----
        ull accL[8];  // [cpair(0:xy,1:zw)][e]
#pragma unroll
        for (int e = 0; e < 4; e++) {
            const float4 gA = *(const float4*)&hA[rowv[e] * HID + 4 * fg];
            const float4 gB = *(const float4*)&hB[colv[e] * HID + 4 * fg];
            accL[e]     = pack2(gA.x + gB.x + b1v.x, gA.y + gB.y + b1v.y);
            accL[4 + e] = pack2(gA.z + gB.z + b1v.z, gA.w + gB.w + b1v.w);
        }
#pragma unroll 4
        for (int k = 0; k < ANF; k += 4) {
#pragma unroll
            for (int j = 0; j < 4; j++) {
                const float4 wv = *(const float4*)&w1cT4[fg * W1STR + (k + j) * 4];
                const ull w01 = pack2(wv.x, wv.y);
                const ull w23 = pack2(wv.z, wv.w);
                const float4 av = *(const float4*)&attr_t[(k + j) * ASTR + 4 * eslot];
                accL[0] = fma2(w01, dup2(av.x), accL[0]);
                accL[4] = fma2(w23, dup2(av.x), accL[4]);
                accL[1] = fma2(w01, dup2(av.y), accL[1]);
                accL[5] = fma2(w23, dup2(av.y), accL[5]);
                accL[2] = fma2(w01, dup2(av.z), accL[2]);
                accL[6] = fma2(w23, dup2(av.z), accL[6]);
                accL[3] = fma2(w01, dup2(av.w), accL[3]);
                accL[7] = fma2(w23, dup2(av.w), accL[7]);
            }
        }
        {
            float sv[16];  // [c][e]
#pragma unroll
            for (int e = 0; e < 4; e++) {
                const float2 f0 = unpack2(accL[e]);
                const float2 f1 = unpack2(accL[4 + e]);
                sv[0 * 4 + e] = silu(f0.x);
                sv[1 * 4 + e] = silu(f0.y);
                sv[2 * 4 + e] = silu(f1.x);
                sv[3 * 4 + e] = silu(f1.y);
            }
#pragma unroll
            for (int c = 0; c < 4; c++) {
                *(float4*)&ef1t[(4 * fg + c) * ASTR + 4 * eslot] =
                    make_float4(sv[c * 4 + 0], sv[c * 4 + 1], sv[c * 4 + 2], sv[c * 4 + 3]);
            }
        }
        __syncthreads();                                            // (b)

        // -------- layer 2 --------
        ull acc[8];
#pragma unroll
        for (int e = 0; e < 4; e++) {
            acc[e]     = pack2(b2v.x, b2v.y);
            acc[4 + e] = pack2(b2v.z, b2v.w);
        }
#pragma unroll 4
        for (int k = 0; k < HID; k += 4) {
#pragma unroll
            for (int j = 0; j < 4; j++) {
                const float4 wv = *(const float4*)&w2T4[fg * W4STR + (k + j) * 4];
                const ull w01 = pack2(wv.x, wv.y);
                const ull w23 = pack2(wv.z, wv.w);
                const float4 av = *(const float4*)&ef1t[(k + j) * ASTR + 4 * eslot];
                acc[0] = fma2(w01, dup2(av.x), acc[0]);
                acc[4] = fma2(w23, dup2(av.x), acc[4]);
                acc[1] = fma2(w01, dup2(av.y), acc[1]);
                acc[5] = fma2(w23, dup2(av.y), acc[5]);
                acc[2] = fma2(w01, dup2(av.z), acc[2]);
                acc[6] = fma2(w23, dup2(av.z), acc[6]);
                acc[3] = fma2(w01, dup2(av.w), acc[3]);
                acc[7] = fma2(w23, dup2(av.w), acc[7]);
            }
        }
        // epilogue: silu + per-edge vector reduction (no transpose needed)
#pragma unroll
        for (int e = 0; e < 4; e++) {
            const float2 f0 = unpack2(acc[e]);
            const float2 f1 = unpack2(acc[4 + e]);
            red_add_v4(&gsum[rowv[e] * HID + 4 * fg],
                       make_float4(silu(f0.x), silu(f0.y), silu(f1.x), silu(f1.y)));
        }
        // no trailing sync: next group's smem writes are fenced by (a)/(b)
    }
}

// ============================================================================
// Kernel 3: scatter-mean + node MLPs + Gram-Schmidt.  512 threads:
// tid&255 -> branch col (0-127 br1, 128-255 br2), tid>>8 -> node half.
// ============================================================================
#define HSTRIDE 129
#define NODE_SMEM_FLOATS (256 * WSTR + HID * HQS + 32 * HSTRIDE + 2 * 384 + 8 + 96)
__global__ void __launch_bounds__(512, 1)
node_kernel(const float* __restrict__ gsum, const float* __restrict__ gcnt,
            const float* __restrict__ v1_w1, const float* __restrict__ v1_b1,
            const float* __restrict__ v1_w2, const float* __restrict__ v1_b2,
            const float* __restrict__ v2_w1, const float* __restrict__ v2_b1,
            const float* __restrict__ v2_w2, const float* __restrict__ v2_b2,
            float* __restrict__ out) {
    extern __shared__ float s[];
    float* wT   = s;                     // 256*132
    float* nq   = wT + 256 * WSTR;       // 128*20 [k][m]
    float* hid  = nq + HID * HQS;        // 32*129 [(m*2+br)][tl]
    float* w2a  = hid + 32 * HSTRIDE;    // 384
    float* w2b  = w2a + 384;             // 384
    float* b2ab = w2b + 384;             // 8
    float* vecs = b2ab + 8;              // 96
    const int tid = threadIdx.x;
    const int tc = tid & 255;
    const int tl = tid & 127;
    const int nh = tid >> 8;

    for (int i = tid; i < HID * HID; i += 512) {
        const int tt = i & 127, kk = i >> 7;
        wT[tt * WSTR + kk] = v1_w1[kk * HID + tt];
        wT[(HID + tt) * WSTR + kk] = v2_w1[kk * HID + tt];
    }
    for (int i = tid; i < 384; i += 512) { w2a[i] = v1_w2[i]; w2b[i] = v2_w2[i]; }
    if (tid < 3) { b2ab[tid] = v1_b2[tid]; b2ab[4 + tid] = v2_b2[tid]; }
    const float myb = (tc < HID) ? v1_b1[tl] : v2_b1[tl];
    __syncthreads();

    const int ngroups = N_NODES / 16;  // 3125
    for (int g = blockIdx.x; g < ngroups; g += gridDim.x) {
        const int nb = g * 16;
        for (int idx = tid; idx < 16 * HID; idx += 512) {
            const int m = idx >> 7, k = idx & 127;
            const float v = gsum[nb * HID + idx] / fmaxf(gcnt[nb + m], 1.0f);
            nq[k * HQS + m] = v;
        }
        __syncthreads();

        ull a[4];
#pragma unroll
        for (int i = 0; i < 4; i++) a[i] = dup2(myb);
#pragma unroll 4
        for (int k = 0; k < HID; k += 4) {
            const float4 wv = *(const float4*)&wT[tc * WSTR + k];
#pragma unroll
            for (int j = 0; j < 4; j++) {
                const float wj = j == 0 ? wv.x : j == 1 ? wv.y : j == 2 ? wv.z : wv.w;
                const ull wp = dup2(wj);
                const ulonglong2* hp = (const ulonglong2*)&nq[(k + j) * HQS + nh * 8];
                const ulonglong2 q0 = hp[0], q1 = hp[1];
                a[0] = fma2(q0.x, wp, a[0]); a[1] = fma2(q0.y, wp, a[1]);
                a[2] = fma2(q1.x, wp, a[2]); a[3] = fma2(q1.y, wp, a[3]);
            }
        }
        {
            const int br = (tc >> 7) & 1;
#pragma unroll
            for (int i = 0; i < 4; i++) {
                const float2 f = unpack2(a[i]);
                const int m = nh * 8 + 2 * i;
                hid[((m + 0) * 2 + br) * HSTRIDE + tl] = silu(f.x);
                hid[((m + 1) * 2 + br) * HSTRIDE + tl] = silu(f.y);
            }
        }
        __syncthreads();

        if (tid < 96) {
            const int m = tid / 6, r = tid % 6, br = r / 3, j = r % 3;
            const float* hh = &hid[(m * 2 + br) * HSTRIDE];
            const float* ww = br ? w2b : w2a;
            float acc = b2ab[br * 4 + j];
#pragma unroll 8
            for (int tt = 0; tt < HID; tt++) acc += hh[tt] * ww[tt * 3 + j];
            vecs[m * 6 + r] = acc;
        }
        __syncthreads();

        if (tid < 16) {
            const float* v = &vecs[tid * 6];
            float v1x = v[0], v1y = v[1], v1z = v[2];
            float v2x = v[3], v2y = v[4], v2z = v[5];
            float n1 = fmaxf(sqrtf(v1x * v1x + v1y * v1y + v1z * v1z), EPSV);
            v1x /= n1; v1y /= n1; v1z /= n1;
            const float d = v2x * v1x + v2y * v1y + v2z * v1z;
            v2x -= d * v1x; v2y -= d * v1y; v2z -= d * v1z;
            float n2 = fmaxf(sqrtf(v2x * v2x + v2y * v2y + v2z * v2z), EPSV);
            v2x /= n2; v2y /= n2; v2z /= n2;
            const float cx = v1y * v2z - v1z * v2y;
            const float cy = v1z * v2x - v1x * v2z;
            const float cz = v1x * v2y - v1y * v2x;
            float* o = &out[(size_t)(nb + tid) * 9];
            o[0] = v1x; o[1] = v2x; o[2] = cx;
            o[3] = v1y; o[4] = v2y; o[5] = cy;
            o[6] = v1z; o[7] = v2z; o[8] = cz;
        }
        __syncthreads();
    }
}

// ============================================================================
// Launch
// ============================================================================
extern "C" void kernel_launch(void* const* d_in, const int* in_sizes, int n_in,
                              void* d_out, int out_size) {
    const float* h      = (const float*)d_in[0];
    const int*   eidx   = (const int*)d_in[2];
    const float* eattr  = (const float*)d_in[3];
    const float* e_w1   = (const float*)d_in[4];
    const float* e_b1   = (const float*)d_in[5];
    const float* e_w2   = (const float*)d_in[6];
    const float* e_b2   = (const float*)d_in[7];
    const float* v1_w1  = (const float*)d_in[8];
    const float* v1_b1  = (const float*)d_in[9];
    const float* v1_w2  = (const float*)d_in[10];
    const float* v1_b2  = (const float*)d_in[11];
    const float* v2_w1  = (const float*)d_in[12];
    const float* v2_b1  = (const float*)d_in[13];
    const float* v2_w2  = (const float*)d_in[14];
    const float* v2_b2  = (const float*)d_in[15];
    float* out = (float*)d_out;

    float *hA, *hB, *sum, *cnt;
    cudaGetSymbolAddress((void**)&hA, g_hA);
    cudaGetSymbolAddress((void**)&hB, g_hB);
    cudaGetSymbolAddress((void**)&sum, g_sum);
    cudaGetSymbolAddress((void**)&cnt, g_cnt);

    const int hab_smem  = HAB_SMEM_FLOATS * 4;
    const int edge_smem = EDGE_SMEM_FLOATS * 4;
    const int node_smem = NODE_SMEM_FLOATS * 4;
    cudaFuncSetAttribute(hab_kernel, cudaFuncAttributeMaxDynamicSharedMemorySize, hab_smem);
    cudaFuncSetAttribute(edge_kernel, cudaFuncAttributeMaxDynamicSharedMemorySize, edge_smem);
    cudaFuncSetAttribute(node_kernel, cudaFuncAttributeMaxDynamicSharedMemorySize, node_smem);

    cudaMemsetAsync(sum, 0, (size_t)N_NODES * HID * sizeof(float));
    cudaMemsetAsync(cnt, 0, (size_t)N_NODES * sizeof(float));

    hab_kernel<<<148, 512, hab_smem>>>(h, e_w1, hA, hB);
    edge_kernel<<<296, 256, edge_smem>>>(hA, hB, eidx, eidx + N_EDGES, eattr,
                                         e_w1, e_b1, e_w2, e_b2, sum, cnt);
    node_kernel<<<148, 512, node_smem>>>(sum, cnt,
                                         v1_w1, v1_b1, v1_w2, v1_b2,
                                         v2_w1, v2_b1, v2_w2, v2_b2, out);
}